// round 11
// baseline (speedup 1.0000x reference)
#include <cuda_runtime.h>
#include <cuda_fp16.h>
#include <cstdint>

// Problem constants
#define ODIM 4096
#define IDIM 4096
#define MTOT 8192   // B*S = 4*2048
#define SEQ  2048

#define KC 64                  // K elems per chunk (64 fp16 = 128B row = SW128 atom)
#define NCHUNK (IDIM / KC)     // 64
#define F_STAGES 4

// Shared memory layout
#define SMEM_FULL  8           // 4 x 8B full barriers (complete_tx)
#define SMEM_EMPTY 64          // 4 x 8B empty barriers (count=8, lid0-only arrives)
#define SMEM_DATA  1024
#define OP_BYTES   16384       // 128 rows x 128B
#define STAGE_BYTES 49152      // A + B0 + B1
#define SMEM_TOTAL  (1024 + F_STAGES * STAGE_BYTES)   // 197632

// Tiled, pre-swizzled fp16 operands: (row128-tile, kchunk64) = 16KB contiguous.
__device__ uint4 g_Xt[(size_t)MTOT * IDIM / 8];   // 64 MB
__device__ uint4 g_Wt[(size_t)ODIM * IDIM / 8];   // 32 MB

// ---------------------------------------------------------------------------
// helpers
// ---------------------------------------------------------------------------
__device__ __forceinline__ uint32_t smem_u32(const void* p) {
    uint32_t a;
    asm("{ .reg .u64 t; cvta.to.shared.u64 t, %1; cvt.u32.u64 %0, t; }" : "=r"(a) : "l"(p));
    return a;
}

#define SWZ(x) ((x) ^ (((x) >> 3) & 0x70))

__device__ __forceinline__ void bulk_ld(uint32_t dst, const void* src,
                                        uint32_t bytes, uint32_t mbar) {
    asm volatile(
        "cp.async.bulk.shared::cluster.global.mbarrier::complete_tx::bytes "
        "[%0], [%1], %2, [%3];"
        :: "r"(dst), "l"(src), "r"(bytes), "r"(mbar) : "memory");
}

__device__ __forceinline__ void expect_tx(uint32_t mbar, uint32_t bytes) {
    asm volatile("mbarrier.arrive.expect_tx.shared.b64 _, [%0], %1;"
                 :: "r"(mbar), "r"(bytes) : "memory");
}

__device__ __forceinline__ void mbar_init(uint32_t addr, uint32_t cnt) {
    asm volatile("mbarrier.init.shared.b64 [%0], %1;" :: "r"(addr), "r"(cnt) : "memory");
}

__device__ __forceinline__ void mbar_arrive(uint32_t addr) {
    asm volatile("mbarrier.arrive.shared.b64 _, [%0];" :: "r"(addr) : "memory");
}

__device__ __forceinline__ void mbar_wait(uint32_t addr, uint32_t parity) {
    asm volatile(
        "{\n\t.reg .pred P1;\n\t"
        "WAIT_%=:\n\t"
        "mbarrier.try_wait.parity.acquire.cta.shared::cta.b64 P1, [%0], %1, 0x989680;\n\t"
        "@P1 bra.uni DONE_%=;\n\t"
        "bra.uni WAIT_%=;\n\t"
        "DONE_%=:\n\t}"
        :: "r"(addr), "r"(parity) : "memory");
}

__device__ __forceinline__ void ldsm_x4(uint32_t addr, uint32_t& r0, uint32_t& r1,
                                        uint32_t& r2, uint32_t& r3) {
    asm volatile("ldmatrix.sync.aligned.m8n8.x4.shared.b16 {%0,%1,%2,%3}, [%4];"
                 : "=r"(r0), "=r"(r1), "=r"(r2), "=r"(r3) : "r"(addr));
}

// ---------------------------------------------------------------------------
// Prep 1: fake-quantize x -> integer-valued fp16, tiled+swizzled layout.
// ---------------------------------------------------------------------------
__global__ void quant_x_kernel(const float* __restrict__ x,
                               const float* __restrict__ act_scale) {
    int idx = blockIdx.x * blockDim.x + threadIdx.x;
    int m = idx >> 9;            // 512 chunks of 8 elems per row
    int c = idx & 511;
    const float4* xp = reinterpret_cast<const float4*>(x + (size_t)m * IDIM + c * 8);
    float4 v0 = xp[0];
    float4 v1 = xp[1];
    float s = act_scale[m & (SEQ - 1)];
    float inv = __fdiv_rn(1.0f, s);
    float q0 = fminf(fmaxf(rintf(v0.x * inv), -127.f), 127.f);
    float q1 = fminf(fmaxf(rintf(v0.y * inv), -127.f), 127.f);
    float q2 = fminf(fmaxf(rintf(v0.z * inv), -127.f), 127.f);
    float q3 = fminf(fmaxf(rintf(v0.w * inv), -127.f), 127.f);
    float q4 = fminf(fmaxf(rintf(v1.x * inv), -127.f), 127.f);
    float q5 = fminf(fmaxf(rintf(v1.y * inv), -127.f), 127.f);
    float q6 = fminf(fmaxf(rintf(v1.z * inv), -127.f), 127.f);
    float q7 = fminf(fmaxf(rintf(v1.w * inv), -127.f), 127.f);
    __half2 h0 = __floats2half2_rn(q0, q1);
    __half2 h1 = __floats2half2_rn(q2, q3);
    __half2 h2 = __floats2half2_rn(q4, q5);
    __half2 h3 = __floats2half2_rn(q6, q7);
    uint4 pk;
    pk.x = *reinterpret_cast<uint32_t*>(&h0);
    pk.y = *reinterpret_cast<uint32_t*>(&h1);
    pk.z = *reinterpret_cast<uint32_t*>(&h2);
    pk.w = *reinterpret_cast<uint32_t*>(&h3);
    int mt = m >> 7, row = m & 127, kc = c >> 3, cc = c & 7;
    g_Xt[(size_t)(mt * 64 + kc) * 1024 + (SWZ((uint32_t)(row * 128 + cc * 16)) >> 4)] = pk;
}

// ---------------------------------------------------------------------------
// Prep 2: dequantize 4-bit weights -> fp16, tiled+swizzled layout.
// ---------------------------------------------------------------------------
__global__ void dequant_w_kernel(const int* __restrict__ qw,
                                 const float* __restrict__ wscale,
                                 const int* __restrict__ wzero) {
    int idx = blockIdx.x * blockDim.x + threadIdx.x;
    int o = idx >> 9;
    int c = idx & 511;
    int4 q = reinterpret_cast<const int4*>(qw + (size_t)o * (IDIM / 2) + c * 4)[0];
    int g = c >> 4;
    float z  = (float)wzero[o * 32 + g];
    float ws = wscale[o * 32 + g];
    __half2 h0 = __floats2half2_rn(((float)(q.x & 15) - z) * ws,
                                   ((float)((q.x >> 4) & 15) - z) * ws);
    __half2 h1 = __floats2half2_rn(((float)(q.y & 15) - z) * ws,
                                   ((float)((q.y >> 4) & 15) - z) * ws);
    __half2 h2 = __floats2half2_rn(((float)(q.z & 15) - z) * ws,
                                   ((float)((q.z >> 4) & 15) - z) * ws);
    __half2 h3 = __floats2half2_rn(((float)(q.w & 15) - z) * ws,
                                   ((float)((q.w >> 4) & 15) - z) * ws);
    uint4 pk;
    pk.x = *reinterpret_cast<uint32_t*>(&h0);
    pk.y = *reinterpret_cast<uint32_t*>(&h1);
    pk.z = *reinterpret_cast<uint32_t*>(&h2);
    pk.w = *reinterpret_cast<uint32_t*>(&h3);
    int nt = o >> 7, row = o & 127, kc = c >> 3, cc = c & 7;
    g_Wt[(size_t)(nt * 64 + kc) * 1024 + (SWZ((uint32_t)(row * 128 + cc * 16)) >> 4)] = pk;
}

// ---------------------------------------------------------------------------
// GEMM: out[m,n] = s[m] * sum_k X[m,k]*W[n,k] + bias[n]
// fp16 mma.sync m16n8k16, CTA 128x256, 8 warps x (64x64), 4-stage bulk pipeline.
// ---------------------------------------------------------------------------
__global__ void __launch_bounds__(256, 1)
gemm_f16_kernel(const float* __restrict__ act_scale,
                const float* __restrict__ bias,
                float* __restrict__ out) {
    extern __shared__ char smem[];
    uint32_t sbase = smem_u32(smem);
    int tid = threadIdx.x;
    int wid = tid >> 5;
    int lid = tid & 31;

    int mt = blockIdx.x >> 4;          // 64 m-tiles (consecutive CTAs share A tile)
    int nt = blockIdx.x & 15;          // 16 n-tiles of 256
    int m0 = mt * 128;
    int n0 = nt * 256;
    int wm = wid & 1;
    int wn = wid >> 1;

    if (tid == 0) {
#pragma unroll
        for (int s = 0; s < F_STAGES; ++s) {
            mbar_init(sbase + SMEM_FULL + 8 * s, 1u);
            mbar_init(sbase + SMEM_EMPTY + 8 * s, 8u);   // one arrive per warp (lid0)
        }
    }
    __syncthreads();

    const char* Asrc  = reinterpret_cast<const char*>(g_Xt) + (size_t)mt * 64 * OP_BYTES;
    const char* B0src = reinterpret_cast<const char*>(g_Wt) + (size_t)(2 * nt) * 64 * OP_BYTES;
    const char* B1src = reinterpret_cast<const char*>(g_Wt) + (size_t)(2 * nt + 1) * 64 * OP_BYTES;

    if (tid == 0) {
#pragma unroll
        for (int k = 0; k < F_STAGES; ++k) {
            uint32_t fb  = sbase + SMEM_FULL + 8 * k;
            uint32_t stg = sbase + SMEM_DATA + k * STAGE_BYTES;
            expect_tx(fb, 3 * OP_BYTES);
            bulk_ld(stg,                Asrc  + (size_t)k * OP_BYTES, OP_BYTES, fb);
            bulk_ld(stg + OP_BYTES,     B0src + (size_t)k * OP_BYTES, OP_BYTES, fb);
            bulk_ld(stg + 2 * OP_BYTES, B1src + (size_t)k * OP_BYTES, OP_BYTES, fb);
        }
    }

    // Lane-constant ldmatrix address components.
    int lrow = lid & 15;
    uint32_t lcol16 = (uint32_t)((lid >> 4) * 16);
    uint32_t aRow0 = (uint32_t)((wm * 64 + lrow) * 128);
    uint32_t aXor  = (uint32_t)((lrow & 7) << 4);
    // B: n = wn*64 + p*16 + lrow ; (n>>7) picks B0/B1 half.
    uint32_t bOff[4];
#pragma unroll
    for (int p = 0; p < 4; ++p) {
        int nl = wn * 64 + p * 16 + lrow;
        bOff[p] = (uint32_t)((nl >> 7) * OP_BYTES + (nl & 127) * 128);
    }
    uint32_t bXor = aXor;

    float acc[4][8][4];
#pragma unroll
    for (int t = 0; t < 4; ++t)
#pragma unroll
        for (int u = 0; u < 8; ++u)
#pragma unroll
            for (int e = 0; e < 4; ++e) acc[t][u][e] = 0.0f;

    for (int k = 0; k < NCHUNK; ++k) {
        int st = k & (F_STAGES - 1);
        uint32_t par = (uint32_t)((k >> 2) & 1);
        mbar_wait(sbase + SMEM_FULL + 8 * st, par);

        uint32_t sA = sbase + SMEM_DATA + st * STAGE_BYTES;
        uint32_t sB = sA + OP_BYTES;

#pragma unroll
        for (int ks = 0; ks < 4; ++ks) {
            uint32_t cb = (uint32_t)(ks * 32) + lcol16;
            uint32_t a[4][4];
#pragma unroll
            for (int t = 0; t < 4; ++t)
                ldsm_x4(sA + aRow0 + (uint32_t)(t * 2048) + (cb ^ aXor),
                        a[t][0], a[t][1], a[t][2], a[t][3]);
            uint32_t b[8][2];
#pragma unroll
            for (int p = 0; p < 4; ++p) {
                uint32_t r0, r1, r2, r3;
                ldsm_x4(sB + bOff[p] + (cb ^ bXor), r0, r1, r2, r3);
                b[2 * p][0] = r0;     b[2 * p][1] = r2;
                b[2 * p + 1][0] = r1; b[2 * p + 1][1] = r3;
            }
#pragma unroll
            for (int t = 0; t < 4; ++t)
#pragma unroll
                for (int u = 0; u < 8; ++u) {
                    asm volatile(
                        "mma.sync.aligned.m16n8k16.row.col.f32.f16.f16.f32 "
                        "{%0,%1,%2,%3}, {%4,%5,%6,%7}, {%8,%9}, {%0,%1,%2,%3};"
                        : "+f"(acc[t][u][0]), "+f"(acc[t][u][1]),
                          "+f"(acc[t][u][2]), "+f"(acc[t][u][3])
                        : "r"(a[t][0]), "r"(a[t][1]), "r"(a[t][2]), "r"(a[t][3]),
                          "r"(b[u][0]), "r"(b[u][1]));
                }
        }

        if (lid == 0) mbar_arrive(sbase + SMEM_EMPTY + 8 * st);   // 8 arrives, not 256
        if (tid == 0 && k + F_STAGES < NCHUNK) {
            mbar_wait(sbase + SMEM_EMPTY + 8 * st, par);
            uint32_t fb  = sbase + SMEM_FULL + 8 * st;
            uint32_t stg = sbase + SMEM_DATA + st * STAGE_BYTES;
            int kn = k + F_STAGES;
            expect_tx(fb, 3 * OP_BYTES);
            bulk_ld(stg,                Asrc  + (size_t)kn * OP_BYTES, OP_BYTES, fb);
            bulk_ld(stg + OP_BYTES,     B0src + (size_t)kn * OP_BYTES, OP_BYTES, fb);
            bulk_ld(stg + 2 * OP_BYTES, B1src + (size_t)kn * OP_BYTES, OP_BYTES, fb);
        }
    }

    // Epilogue: d-frag (t,u): rows m0+wm*64+16t+qr (+8), cols n0+wn*64+8u+qc (+1).
    int qr = lid >> 2;
    int qc = (lid & 3) * 2;
#pragma unroll
    for (int t = 0; t < 4; ++t) {
        int mA = m0 + wm * 64 + t * 16 + qr;
        int mB = mA + 8;
        float sA_ = act_scale[mA & (SEQ - 1)];
        float sB_ = act_scale[mB & (SEQ - 1)];
#pragma unroll
        for (int u = 0; u < 8; ++u) {
            int n = n0 + wn * 64 + u * 8 + qc;
            float b0 = bias[n], b1 = bias[n + 1];
            float2 v0, v1;
            v0.x = acc[t][u][0] * sA_ + b0;
            v0.y = acc[t][u][1] * sA_ + b1;
            v1.x = acc[t][u][2] * sB_ + b0;
            v1.y = acc[t][u][3] * sB_ + b1;
            *reinterpret_cast<float2*>(out + (size_t)mA * ODIM + n) = v0;
            *reinterpret_cast<float2*>(out + (size_t)mB * ODIM + n) = v1;
        }
    }
}

// ---------------------------------------------------------------------------
extern "C" void kernel_launch(void* const* d_in, const int* in_sizes, int n_in,
                              void* d_out, int out_size) {
    const float* x            = (const float*)d_in[0];
    const int*   qweight      = (const int*)d_in[1];
    const float* act_scale    = (const float*)d_in[2];
    const float* weight_scale = (const float*)d_in[3];
    const int*   weight_zero  = (const int*)d_in[4];
    const float* bias         = (const float*)d_in[5];
    float* out = (float*)d_out;

    cudaFuncSetAttribute(gemm_f16_kernel,
                         cudaFuncAttributeMaxDynamicSharedMemorySize, SMEM_TOTAL);

    quant_x_kernel<<<(MTOT * IDIM / 8) / 256, 256>>>(x, act_scale);
    dequant_w_kernel<<<(ODIM * IDIM / 8) / 256, 256>>>(qweight, weight_scale, weight_zero);
    gemm_f16_kernel<<<(MTOT / 128) * (ODIM / 256), 256, SMEM_TOTAL>>>(act_scale, bias, out);
}